// round 4
// baseline (speedup 1.0000x reference)
#include <cuda_runtime.h>
#include <cuda_bf16.h>
#include <math.h>
#include <stdint.h>

// Problem constants
#define Bk 128
#define Sk 200
#define Dk 512
#define Hk 8
#define DFk 64
#define ROWS (Bk * Sk)          // 25600
#define SCALE 0.125f

typedef __nv_bfloat16 bf16;

// ---------------- device scratch ----------------
__device__ __align__(256) float g_Qp[(size_t)ROWS * Dk];
__device__ __align__(256) float g_Kp[(size_t)ROWS * Dk];
__device__ __align__(256) float g_Vp[(size_t)ROWS * Dk];
__device__ __align__(256) bf16  g_xhi[3][(size_t)ROWS * Dk];   // q,k,v split-hi
__device__ __align__(256) bf16  g_xlo[3][(size_t)ROWS * Dk];   // q,k,v split-lo
__device__ __align__(256) bf16  g_whi[4][(size_t)Dk * Dk];     // Wq,Wk,Wv,Wo hi
__device__ __align__(256) bf16  g_wlo[4][(size_t)Dk * Dk];     // lo
__device__ __align__(256) bf16  g_chi[(size_t)ROWS * Dk];      // ctx hi
__device__ __align__(256) bf16  g_clo[(size_t)ROWS * Dk];      // ctx lo

// ---------------- mma.sync + cp.async helpers (base sm_103 target) ----------
#define MMA16816(d, a, b)                                                      \
    asm volatile(                                                              \
        "mma.sync.aligned.m16n8k16.row.col.f32.bf16.bf16.f32 "                 \
        "{%0,%1,%2,%3}, {%4,%5,%6,%7}, {%8,%9}, {%0,%1,%2,%3};"                \
        : "+f"((d)[0]), "+f"((d)[1]), "+f"((d)[2]), "+f"((d)[3])               \
        : "r"((a)[0]), "r"((a)[1]), "r"((a)[2]), "r"((a)[3]),                  \
          "r"((b)[0]), "r"((b)[1]))

static __device__ __forceinline__ void cp_async16(uint32_t saddr, const void* gaddr) {
    asm volatile("cp.async.cg.shared.global [%0], [%1], 16;"
                 :: "r"(saddr), "l"(gaddr));
}
static __device__ __forceinline__ void cp_commit() {
    asm volatile("cp.async.commit_group;" ::: "memory");
}
template <int N>
static __device__ __forceinline__ void cp_wait() {
    asm volatile("cp.async.wait_group %0;" :: "n"(N) : "memory");
}

// ---------------- GEMM config ----------------
// C[M,N] = X[M,512] * W[N,512]^T, 3-split bf16.
// CTA 128x128, BK=32, 8 warps (2 m x 4 n), warp tile 64x32.
#define BKC 32
#define NCH (Dk / BKC)          // 16 chunks
#define ROWE 40                 // padded row length in bf16 (80 B)
#define TILE_B (128 * ROWE * 2) // 10240 bytes per sub-tile
#define STG_B  (4 * TILE_B)     // Ah, Al, Bh, Bl = 40960 bytes per stage
#define GEMM_SMEM (2 * STG_B)   // 81920

// Load one K-chunk (32 cols) of Ah/Al/Bh/Bl into stage via cp.async.
static __device__ __forceinline__ void load_chunk(
    char* stage, const bf16* __restrict__ Ah, const bf16* __restrict__ Al,
    const bf16* __restrict__ Bh, const bf16* __restrict__ Bl, int k0)
{
    const bf16* bases[4] = {Ah, Al, Bh, Bl};
    const int tid = threadIdx.x;
    uint32_t sbase = (uint32_t)__cvta_generic_to_shared(stage);
#pragma unroll
    for (int j = 0; j < 8; j++) {
        const int idx  = tid + j * 256;       // 0..2047
        const int tile = idx >> 9;
        const int w    = idx & 511;
        const int r    = w >> 2;
        const int c16  = w & 3;
        const bf16* g = bases[tile] + (size_t)r * Dk + k0 + c16 * 8;
        uint32_t s = sbase + tile * TILE_B + r * (ROWE * 2) + c16 * 16;
        cp_async16(s, g);
    }
}

struct WAcc { float v[4][4][4]; };   // [mf][nf][c0..c3]

// Full 3-split mainloop; acc must be zero-initialized by caller.
static __device__ __forceinline__ void mma_mainloop(
    const bf16* __restrict__ Ahi, const bf16* __restrict__ Alo,
    const bf16* __restrict__ Bhi, const bf16* __restrict__ Blo,
    int m0, int n0, char* smem, WAcc& acc)
{
    const int tid   = threadIdx.x;
    const int wid   = tid >> 5;
    const int lane  = tid & 31;
    const int warpM = wid >> 2;          // 0..1
    const int warpN = wid & 3;           // 0..3
    const int g     = lane >> 2;         // 0..7
    const int q     = lane & 3;          // 0..3

    const bf16* Ah = Ahi + (size_t)m0 * Dk;
    const bf16* Al = Alo + (size_t)m0 * Dk;
    const bf16* Bh = Bhi + (size_t)n0 * Dk;
    const bf16* Bl = Blo + (size_t)n0 * Dk;

    load_chunk(smem, Ah, Al, Bh, Bl, 0);
    cp_commit();

    for (int c = 0; c < NCH; c++) {
        if (c + 1 < NCH) {
            load_chunk(smem + ((c + 1) & 1) * STG_B, Ah, Al, Bh, Bl, (c + 1) * BKC);
            cp_commit();
            cp_wait<1>();
        } else {
            cp_wait<0>();
        }
        __syncthreads();

        const char* stg = smem + (c & 1) * STG_B;
        // byte offsets into a tile: row*80 + kh*32 + q*4 (+16 for hi-k regs)
#pragma unroll
        for (int kh = 0; kh < 2; kh++) {
            uint32_t bh[4][2], bl[4][2];
#pragma unroll
            for (int nf = 0; nf < 4; nf++) {
                const int n = warpN * 32 + nf * 8 + g;
                const int o = n * (ROWE * 2) + kh * 32 + q * 4;
                bh[nf][0] = *(const uint32_t*)(stg + 2 * TILE_B + o);
                bh[nf][1] = *(const uint32_t*)(stg + 2 * TILE_B + o + 16);
                bl[nf][0] = *(const uint32_t*)(stg + 3 * TILE_B + o);
                bl[nf][1] = *(const uint32_t*)(stg + 3 * TILE_B + o + 16);
            }
#pragma unroll
            for (int mf = 0; mf < 4; mf++) {
                const int r = warpM * 64 + mf * 16 + g;
                const int o = r * (ROWE * 2) + kh * 32 + q * 4;
                uint32_t ah[4], al[4];
                ah[0] = *(const uint32_t*)(stg + o);
                ah[1] = *(const uint32_t*)(stg + o + 8 * (ROWE * 2));
                ah[2] = *(const uint32_t*)(stg + o + 16);
                ah[3] = *(const uint32_t*)(stg + o + 8 * (ROWE * 2) + 16);
                al[0] = *(const uint32_t*)(stg + TILE_B + o);
                al[1] = *(const uint32_t*)(stg + TILE_B + o + 8 * (ROWE * 2));
                al[2] = *(const uint32_t*)(stg + TILE_B + o + 16);
                al[3] = *(const uint32_t*)(stg + TILE_B + o + 8 * (ROWE * 2) + 16);
#pragma unroll
                for (int nf = 0; nf < 4; nf++) {
                    MMA16816(acc.v[mf][nf], ah, bh[nf]);
                    MMA16816(acc.v[mf][nf], ah, bl[nf]);
                    MMA16816(acc.v[mf][nf], al, bh[nf]);
                }
            }
        }
        __syncthreads();
    }
}

// ---------------- QKV projection (scatter to [B,H,S,DF]) ----------------
__global__ __launch_bounds__(256, 1)
void qkv_mma_kernel(const float* __restrict__ bq, const float* __restrict__ bk,
                    const float* __restrict__ bv)
{
    extern __shared__ char smem[];
    const int z  = blockIdx.z;
    const int m0 = blockIdx.y * 128;
    const int n0 = blockIdx.x * 128;

    WAcc acc;
#pragma unroll
    for (int a = 0; a < 4; a++)
#pragma unroll
        for (int b = 0; b < 4; b++)
#pragma unroll
            for (int cc = 0; cc < 4; cc++) acc.v[a][b][cc] = 0.f;

    mma_mainloop(g_xhi[z], g_xlo[z], g_whi[z], g_wlo[z], m0, n0, smem, acc);

    const float* bias = (z == 0) ? bq : (z == 1) ? bk : bv;
    float* out        = (z == 0) ? g_Qp : (z == 1) ? g_Kp : g_Vp;

    const int lane  = threadIdx.x & 31;
    const int wid   = threadIdx.x >> 5;
    const int warpM = wid >> 2, warpN = wid & 3;
    const int g     = lane >> 2, q = lane & 3;

#pragma unroll
    for (int mf = 0; mf < 4; mf++) {
#pragma unroll
        for (int half = 0; half < 2; half++) {
            const int m  = m0 + warpM * 64 + mf * 16 + g + half * 8;
            const int bb = m / Sk;
            const int ss = m - bb * Sk;
            const size_t rowbase = ((size_t)bb * Hk) * Sk * DFk + (size_t)ss * DFk;
#pragma unroll
            for (int nf = 0; nf < 4; nf++) {
#pragma unroll
                for (int e = 0; e < 2; e++) {
                    const int n  = n0 + warpN * 32 + nf * 8 + q * 2 + e;
                    const int hh = n >> 6;
                    const int df = n & 63;
                    out[rowbase + (size_t)hh * Sk * DFk + df] =
                        acc.v[mf][nf][half * 2 + e] + bias[n];
                }
            }
        }
    }
}

// ---------------- output projection ----------------
__global__ __launch_bounds__(256, 1)
void out_mma_kernel(const float* __restrict__ bo, float* __restrict__ out)
{
    extern __shared__ char smem[];
    const int m0 = blockIdx.y * 128;
    const int n0 = blockIdx.x * 128;

    WAcc acc;
#pragma unroll
    for (int a = 0; a < 4; a++)
#pragma unroll
        for (int b = 0; b < 4; b++)
#pragma unroll
            for (int cc = 0; cc < 4; cc++) acc.v[a][b][cc] = 0.f;

    mma_mainloop(g_chi, g_clo, g_whi[3], g_wlo[3], m0, n0, smem, acc);

    const int lane  = threadIdx.x & 31;
    const int wid   = threadIdx.x >> 5;
    const int warpM = wid >> 2, warpN = wid & 3;
    const int g     = lane >> 2, q = lane & 3;

#pragma unroll
    for (int mf = 0; mf < 4; mf++) {
#pragma unroll
        for (int half = 0; half < 2; half++) {
            const int m = m0 + warpM * 64 + mf * 16 + g + half * 8;
#pragma unroll
            for (int nf = 0; nf < 4; nf++) {
                const int n = n0 + warpN * 32 + nf * 8 + q * 2;
                float2 v;
                v.x = acc.v[mf][nf][half * 2 + 0] + bo[n];
                v.y = acc.v[mf][nf][half * 2 + 1] + bo[n + 1];
                *(float2*)(out + (size_t)m * Dk + n) = v;
            }
        }
    }
}

// ---------------- fp32 -> bf16 hi/lo split ----------------
__global__ void cvt_kernel(const float* __restrict__ x, int which, int n4)
{
    const int i = blockIdx.x * blockDim.x + threadIdx.x;
    if (i >= n4) return;
    bf16* hi = (which < 3) ? g_xhi[which] : g_whi[which - 3];
    bf16* lo = (which < 3) ? g_xlo[which] : g_wlo[which - 3];
    float4 v = ((const float4*)x)[i];
    bf16 h0 = __float2bfloat16(v.x), h1 = __float2bfloat16(v.y);
    bf16 h2 = __float2bfloat16(v.z), h3 = __float2bfloat16(v.w);
    bf16 l0 = __float2bfloat16(v.x - __bfloat162float(h0));
    bf16 l1 = __float2bfloat16(v.y - __bfloat162float(h1));
    bf16 l2 = __float2bfloat16(v.z - __bfloat162float(h2));
    bf16 l3 = __float2bfloat16(v.w - __bfloat162float(h3));
    ((__nv_bfloat162*)hi)[2 * i]     = __halves2bfloat162(h0, h1);
    ((__nv_bfloat162*)hi)[2 * i + 1] = __halves2bfloat162(h2, h3);
    ((__nv_bfloat162*)lo)[2 * i]     = __halves2bfloat162(l0, l1);
    ((__nv_bfloat162*)lo)[2 * i + 1] = __halves2bfloat162(l2, l3);
}

// ---------------- attention (fp32; writes bf16 hi/lo ctx) ----------------
#define KV_LD 65
#define ATTN_SMEM_FLOATS (2 * Sk * KV_LD + 8 * Sk + 8 * DFk)

__global__ __launch_bounds__(256, 2)
void attn_kernel()
{
    extern __shared__ float sm[];
    float* Ks = sm;
    float* Vs = Ks + Sk * KV_LD;
    float* Ps = Vs + Sk * KV_LD;
    float* Qs = Ps + 8 * Sk;

    const int bh = blockIdx.x;
    const int bb = bh >> 3;
    const int hh = bh & 7;
    const size_t base = (size_t)bh * Sk * DFk;
    const float* Qg = g_Qp + base;
    const float* Kg = g_Kp + base;
    const float* Vg = g_Vp + base;

    const int tid = threadIdx.x;
    for (int i = tid; i < Sk * DFk; i += 256) {
        const int r = i >> 6;
        const int c = i & 63;
        Ks[r * KV_LD + c] = Kg[i];
        Vs[r * KV_LD + c] = Vg[i];
    }
    __syncthreads();

    const int w    = tid >> 5;
    const int lane = tid & 31;
    float* Pw = Ps + w * Sk;

    for (int qi = w; qi < Sk; qi += 8) {
        Qs[w * DFk + lane]      = Qg[qi * DFk + lane];
        Qs[w * DFk + 32 + lane] = Qg[qi * DFk + 32 + lane];
        __syncwarp();
        float qreg[DFk];
#pragma unroll
        for (int d = 0; d < DFk; d++) qreg[d] = Qs[w * DFk + d];

        const int nk = qi + 1;
        float sc[7];
        float mx = -INFINITY;
        int cnt = 0;
        for (int kk = lane; kk < nk; kk += 32) {
            const float* kr = Ks + kk * KV_LD;
            float s = 0.f;
#pragma unroll
            for (int d = 0; d < DFk; d++) s = fmaf(qreg[d], kr[d], s);
            s *= SCALE;
            sc[cnt++] = s;
            mx = fmaxf(mx, s);
        }
#pragma unroll
        for (int off = 16; off > 0; off >>= 1)
            mx = fmaxf(mx, __shfl_xor_sync(0xFFFFFFFFu, mx, off));

        float lsum = 0.f;
        cnt = 0;
        for (int kk = lane; kk < nk; kk += 32) {
            float e = expf(sc[cnt++] - mx);
            Pw[kk] = e;
            lsum += e;
        }
#pragma unroll
        for (int off = 16; off > 0; off >>= 1)
            lsum += __shfl_xor_sync(0xFFFFFFFFu, lsum, off);
        const float inv = 1.f / lsum;
        __syncwarp();

        float a0 = 0.f, a1 = 0.f;
        for (int kk = 0; kk < nk; kk++) {
            const float p = Pw[kk];
            a0 = fmaf(p, Vs[kk * KV_LD + lane],      a0);
            a1 = fmaf(p, Vs[kk * KV_LD + 32 + lane], a1);
        }
        a0 *= inv; a1 *= inv;
        if (qi == 0) { a0 = 0.f; a1 = 0.f; }

        const size_t o = ((size_t)bb * Sk + qi) * Dk + hh * DFk;
        bf16 h0 = __float2bfloat16(a0);
        bf16 h1 = __float2bfloat16(a1);
        g_chi[o + lane]      = h0;
        g_chi[o + lane + 32] = h1;
        g_clo[o + lane]      = __float2bfloat16(a0 - __bfloat162float(h0));
        g_clo[o + lane + 32] = __float2bfloat16(a1 - __bfloat162float(h1));
        __syncwarp();
    }
}

// ---------------- launch ----------------
extern "C" void kernel_launch(void* const* d_in, const int* in_sizes, int n_in,
                              void* d_out, int out_size)
{
    const float* q  = (const float*)d_in[0];
    const float* k  = (const float*)d_in[1];
    const float* v  = (const float*)d_in[2];
    const float* Wq = (const float*)d_in[3];
    const float* bq = (const float*)d_in[4];
    const float* Wk = (const float*)d_in[5];
    const float* bk = (const float*)d_in[6];
    const float* Wv = (const float*)d_in[7];
    const float* bv = (const float*)d_in[8];
    const float* Wo = (const float*)d_in[9];
    const float* bo = (const float*)d_in[10];
    float* out = (float*)d_out;

    const int nx4 = ROWS * Dk / 4;
    const int nw4 = Dk * Dk / 4;
    cvt_kernel<<<nx4 / 256, 256>>>(q,  0, nx4);
    cvt_kernel<<<nx4 / 256, 256>>>(k,  1, nx4);
    cvt_kernel<<<nx4 / 256, 256>>>(v,  2, nx4);
    cvt_kernel<<<nw4 / 256, 256>>>(Wq, 3, nw4);
    cvt_kernel<<<nw4 / 256, 256>>>(Wk, 4, nw4);
    cvt_kernel<<<nw4 / 256, 256>>>(Wv, 5, nw4);
    cvt_kernel<<<nw4 / 256, 256>>>(Wo, 6, nw4);

    cudaFuncSetAttribute(qkv_mma_kernel, cudaFuncAttributeMaxDynamicSharedMemorySize,
                         GEMM_SMEM);
    qkv_mma_kernel<<<dim3(Dk / 128, ROWS / 128, 3), 256, GEMM_SMEM>>>(bq, bk, bv);

    const int attn_smem = ATTN_SMEM_FLOATS * (int)sizeof(float);
    cudaFuncSetAttribute(attn_kernel, cudaFuncAttributeMaxDynamicSharedMemorySize,
                         attn_smem);
    attn_kernel<<<Bk * Hk, 256, attn_smem>>>();

    cudaFuncSetAttribute(out_mma_kernel, cudaFuncAttributeMaxDynamicSharedMemorySize,
                         GEMM_SMEM);
    out_mma_kernel<<<dim3(Dk / 128, ROWS / 128, 1), 256, GEMM_SMEM>>>(bo, out);
}

// round 5
// speedup vs baseline: 1.1046x; 1.1046x over previous
#include <cuda_runtime.h>
#include <cuda_bf16.h>
#include <math.h>
#include <stdint.h>

#define Bk 128
#define Sk 200
#define Dk 512
#define Hk 8
#define DFk 64
#define ROWS (Bk * Sk)          // 25600
#define SCALE 0.125f

typedef __nv_bfloat16 bf16;

// ---------------- device scratch ----------------
__device__ __align__(256) float g_Qp[(size_t)ROWS * Dk];
__device__ __align__(256) float g_Kp[(size_t)ROWS * Dk];
__device__ __align__(256) float g_Vp[(size_t)ROWS * Dk];
__device__ __align__(256) bf16  g_xhi[3][(size_t)ROWS * Dk];
__device__ __align__(256) bf16  g_xlo[3][(size_t)ROWS * Dk];
__device__ __align__(256) bf16  g_whi[4][(size_t)Dk * Dk];
__device__ __align__(256) bf16  g_wlo[4][(size_t)Dk * Dk];
__device__ __align__(256) bf16  g_chi[(size_t)ROWS * Dk];
__device__ __align__(256) bf16  g_clo[(size_t)ROWS * Dk];

// ---------------- mma.sync + cp.async helpers ----------------
#define MMA16816(d, a, b)                                                      \
    asm volatile(                                                              \
        "mma.sync.aligned.m16n8k16.row.col.f32.bf16.bf16.f32 "                 \
        "{%0,%1,%2,%3}, {%4,%5,%6,%7}, {%8,%9}, {%0,%1,%2,%3};"                \
        : "+f"((d)[0]), "+f"((d)[1]), "+f"((d)[2]), "+f"((d)[3])               \
        : "r"((a)[0]), "r"((a)[1]), "r"((a)[2]), "r"((a)[3]),                  \
          "r"((b)[0]), "r"((b)[1]))

static __device__ __forceinline__ void cp_async16(uint32_t saddr, const void* gaddr) {
    asm volatile("cp.async.cg.shared.global [%0], [%1], 16;"
                 :: "r"(saddr), "l"(gaddr));
}
static __device__ __forceinline__ void cp_commit() {
    asm volatile("cp.async.commit_group;" ::: "memory");
}
template <int N>
static __device__ __forceinline__ void cp_wait() {
    asm volatile("cp.async.wait_group %0;" :: "n"(N) : "memory");
}

// ---------------- GEMM config: 512 threads, CTA 128x256, BK=32 ----------------
#define BKC 32
#define NCH (Dk / BKC)          // 16
#define SA_HI 0
#define SA_LO 10240
#define SB_HI 20480
#define SB_LO 40960
#define STG_B 61440
#define GEMM_SMEM (2 * STG_B)   // 122880

// A: 128 rows x 32 cols (hi+lo), B: 256 rows x 32 cols (hi+lo); 80 B padded rows
static __device__ __forceinline__ void load_chunk(
    char* stage, const bf16* __restrict__ Ah, const bf16* __restrict__ Al,
    const bf16* __restrict__ Bh, const bf16* __restrict__ Bl, int k0)
{
    const int tid = threadIdx.x;
    uint32_t sbase = (uint32_t)__cvta_generic_to_shared(stage);
#pragma unroll
    for (int j = 0; j < 6; j++) {
        const int idx = tid + j * 512;     // 0..3071
        if (idx < 1024) {
            const int sp = idx >> 9;
            const int w  = idx & 511;
            const int r  = w >> 2;
            const int c  = w & 3;
            const bf16* g = (sp ? Al : Ah) + (size_t)r * Dk + k0 + c * 8;
            cp_async16(sbase + (sp ? SA_LO : SA_HI) + r * 80 + c * 16, g);
        } else {
            const int t  = idx - 1024;
            const int sp = t >> 10;
            const int w  = t & 1023;
            const int r  = w >> 2;
            const int c  = w & 3;
            const bf16* g = (sp ? Bl : Bh) + (size_t)r * Dk + k0 + c * 8;
            cp_async16(sbase + (sp ? SB_LO : SB_HI) + r * 80 + c * 16, g);
        }
    }
}

struct WAcc { float v[4][4][4]; };

static __device__ __forceinline__ void mma_mainloop(
    const bf16* __restrict__ Ahi, const bf16* __restrict__ Alo,
    const bf16* __restrict__ Bhi, const bf16* __restrict__ Blo,
    int m0, int n0, char* smem, WAcc& acc)
{
    const int tid   = threadIdx.x;
    const int wid   = tid >> 5;
    const int lane  = tid & 31;
    const int warpM = wid >> 3;          // 0..1
    const int warpN = wid & 7;           // 0..7
    const int g     = lane >> 2;
    const int q     = lane & 3;

    const bf16* Ah = Ahi + (size_t)m0 * Dk;
    const bf16* Al = Alo + (size_t)m0 * Dk;
    const bf16* Bh = Bhi + (size_t)n0 * Dk;
    const bf16* Bl = Blo + (size_t)n0 * Dk;

    load_chunk(smem, Ah, Al, Bh, Bl, 0);
    cp_commit();

    for (int c = 0; c < NCH; c++) {
        if (c + 1 < NCH) {
            load_chunk(smem + ((c + 1) & 1) * STG_B, Ah, Al, Bh, Bl, (c + 1) * BKC);
            cp_commit();
            cp_wait<1>();
        } else {
            cp_wait<0>();
        }
        __syncthreads();

        const char* stg = smem + (c & 1) * STG_B;
#pragma unroll
        for (int kh = 0; kh < 2; kh++) {
            uint32_t bh_[4][2], bl_[4][2];
#pragma unroll
            for (int nf = 0; nf < 4; nf++) {
                const int n = warpN * 32 + nf * 8 + g;
                const int o = n * 80 + kh * 32 + q * 4;
                bh_[nf][0] = *(const uint32_t*)(stg + SB_HI + o);
                bh_[nf][1] = *(const uint32_t*)(stg + SB_HI + o + 16);
                bl_[nf][0] = *(const uint32_t*)(stg + SB_LO + o);
                bl_[nf][1] = *(const uint32_t*)(stg + SB_LO + o + 16);
            }
#pragma unroll
            for (int mf = 0; mf < 4; mf++) {
                const int r = warpM * 64 + mf * 16 + g;
                const int o = r * 80 + kh * 32 + q * 4;
                uint32_t ah[4], al[4];
                ah[0] = *(const uint32_t*)(stg + SA_HI + o);
                ah[1] = *(const uint32_t*)(stg + SA_HI + o + 640);
                ah[2] = *(const uint32_t*)(stg + SA_HI + o + 16);
                ah[3] = *(const uint32_t*)(stg + SA_HI + o + 656);
                al[0] = *(const uint32_t*)(stg + SA_LO + o);
                al[1] = *(const uint32_t*)(stg + SA_LO + o + 640);
                al[2] = *(const uint32_t*)(stg + SA_LO + o + 16);
                al[3] = *(const uint32_t*)(stg + SA_LO + o + 656);
#pragma unroll
                for (int nf = 0; nf < 4; nf++) {
                    MMA16816(acc.v[mf][nf], ah, bh_[nf]);
                    MMA16816(acc.v[mf][nf], ah, bl_[nf]);
                    MMA16816(acc.v[mf][nf], al, bh_[nf]);
                }
            }
        }
        __syncthreads();
    }
}

// ---------------- QKV projection ----------------
__global__ __launch_bounds__(512, 1)
void qkv_mma_kernel(const float* __restrict__ bq, const float* __restrict__ bk,
                    const float* __restrict__ bv)
{
    extern __shared__ char smem[];
    const int z  = blockIdx.z;
    const int m0 = blockIdx.y * 128;
    const int n0 = blockIdx.x * 256;

    WAcc acc;
#pragma unroll
    for (int a = 0; a < 4; a++)
#pragma unroll
        for (int b = 0; b < 4; b++)
#pragma unroll
            for (int cc = 0; cc < 4; cc++) acc.v[a][b][cc] = 0.f;

    mma_mainloop(g_xhi[z], g_xlo[z], g_whi[z], g_wlo[z], m0, n0, smem, acc);

    const float* bias = (z == 0) ? bq : (z == 1) ? bk : bv;
    float* out        = (z == 0) ? g_Qp : (z == 1) ? g_Kp : g_Vp;

    const int lane  = threadIdx.x & 31;
    const int wid   = threadIdx.x >> 5;
    const int warpM = wid >> 3, warpN = wid & 7;
    const int g     = lane >> 2, q = lane & 3;

#pragma unroll
    for (int mf = 0; mf < 4; mf++) {
#pragma unroll
        for (int half = 0; half < 2; half++) {
            const int m  = m0 + warpM * 64 + mf * 16 + g + half * 8;
            const int bb = m / Sk;
            const int ss = m - bb * Sk;
            const size_t rowbase = ((size_t)bb * Hk) * Sk * DFk + (size_t)ss * DFk;
#pragma unroll
            for (int nf = 0; nf < 4; nf++) {
#pragma unroll
                for (int e = 0; e < 2; e++) {
                    const int n  = n0 + warpN * 32 + nf * 8 + q * 2 + e;
                    const int hh = n >> 6;
                    const int df = n & 63;
                    out[rowbase + (size_t)hh * Sk * DFk + df] =
                        acc.v[mf][nf][half * 2 + e] + bias[n];
                }
            }
        }
    }
}

// ---------------- output projection ----------------
__global__ __launch_bounds__(512, 1)
void out_mma_kernel(const float* __restrict__ bo, float* __restrict__ out)
{
    extern __shared__ char smem[];
    const int m0 = blockIdx.y * 128;
    const int n0 = blockIdx.x * 256;

    WAcc acc;
#pragma unroll
    for (int a = 0; a < 4; a++)
#pragma unroll
        for (int b = 0; b < 4; b++)
#pragma unroll
            for (int cc = 0; cc < 4; cc++) acc.v[a][b][cc] = 0.f;

    mma_mainloop(g_chi, g_clo, g_whi[3], g_wlo[3], m0, n0, smem, acc);

    const int lane  = threadIdx.x & 31;
    const int wid   = threadIdx.x >> 5;
    const int warpM = wid >> 3, warpN = wid & 7;
    const int g     = lane >> 2, q = lane & 3;

#pragma unroll
    for (int mf = 0; mf < 4; mf++) {
#pragma unroll
        for (int half = 0; half < 2; half++) {
            const int m = m0 + warpM * 64 + mf * 16 + g + half * 8;
#pragma unroll
            for (int nf = 0; nf < 4; nf++) {
                const int n = n0 + warpN * 32 + nf * 8 + q * 2;
                float2 v;
                v.x = acc.v[mf][nf][half * 2 + 0] + bo[n];
                v.y = acc.v[mf][nf][half * 2 + 1] + bo[n + 1];
                *(float2*)(out + (size_t)m * Dk + n) = v;
            }
        }
    }
}

// ---------------- fp32 -> bf16 hi/lo split ----------------
__global__ void cvt_kernel(const float* __restrict__ x, int which, int n4)
{
    const int i = blockIdx.x * blockDim.x + threadIdx.x;
    if (i >= n4) return;
    bf16* hi = (which < 3) ? g_xhi[which] : g_whi[which - 3];
    bf16* lo = (which < 3) ? g_xlo[which] : g_wlo[which - 3];
    float4 v = ((const float4*)x)[i];
    bf16 h0 = __float2bfloat16(v.x), h1 = __float2bfloat16(v.y);
    bf16 h2 = __float2bfloat16(v.z), h3 = __float2bfloat16(v.w);
    bf16 l0 = __float2bfloat16(v.x - __bfloat162float(h0));
    bf16 l1 = __float2bfloat16(v.y - __bfloat162float(h1));
    bf16 l2 = __float2bfloat16(v.z - __bfloat162float(h2));
    bf16 l3 = __float2bfloat16(v.w - __bfloat162float(h3));
    ((__nv_bfloat162*)hi)[2 * i]     = __halves2bfloat162(h0, h1);
    ((__nv_bfloat162*)hi)[2 * i + 1] = __halves2bfloat162(h2, h3);
    ((__nv_bfloat162*)lo)[2 * i]     = __halves2bfloat162(l0, l1);
    ((__nv_bfloat162*)lo)[2 * i + 1] = __halves2bfloat162(l2, l3);
}

// ---------------- attention (fp32; writes bf16 hi/lo ctx) ----------------
#define KV_LD 65
#define ATTN_SMEM_FLOATS (2 * Sk * KV_LD + 8 * Sk + 8 * DFk)

__global__ __launch_bounds__(256, 2)
void attn_kernel()
{
    extern __shared__ float sm[];
    float* Ks = sm;
    float* Vs = Ks + Sk * KV_LD;
    float* Ps = Vs + Sk * KV_LD;
    float* Qs = Ps + 8 * Sk;

    const int bh = blockIdx.x;
    const int bb = bh >> 3;
    const int hh = bh & 7;
    const size_t base = (size_t)bh * Sk * DFk;
    const float* Qg = g_Qp + base;
    const float* Kg = g_Kp + base;
    const float* Vg = g_Vp + base;

    const int tid = threadIdx.x;
    for (int i = tid; i < Sk * DFk; i += 256) {
        const int r = i >> 6;
        const int c = i & 63;
        Ks[r * KV_LD + c] = Kg[i];
        Vs[r * KV_LD + c] = Vg[i];
    }
    __syncthreads();

    const int w    = tid >> 5;
    const int lane = tid & 31;
    float* Pw = Ps + w * Sk;

    for (int qi = w; qi < Sk; qi += 8) {
        Qs[w * DFk + lane]      = Qg[qi * DFk + lane];
        Qs[w * DFk + 32 + lane] = Qg[qi * DFk + 32 + lane];
        __syncwarp();
        float qreg[DFk];
#pragma unroll
        for (int d = 0; d < DFk; d++) qreg[d] = Qs[w * DFk + d];

        const int nk = qi + 1;
        float sc[7];
        float mx = -INFINITY;
        int cnt = 0;
        for (int kk = lane; kk < nk; kk += 32) {
            const float* kr = Ks + kk * KV_LD;
            float s = 0.f;
#pragma unroll
            for (int d = 0; d < DFk; d++) s = fmaf(qreg[d], kr[d], s);
            s *= SCALE;
            sc[cnt++] = s;
            mx = fmaxf(mx, s);
        }
#pragma unroll
        for (int off = 16; off > 0; off >>= 1)
            mx = fmaxf(mx, __shfl_xor_sync(0xFFFFFFFFu, mx, off));

        float lsum = 0.f;
        cnt = 0;
        for (int kk = lane; kk < nk; kk += 32) {
            float e = expf(sc[cnt++] - mx);
            Pw[kk] = e;
            lsum += e;
        }
#pragma unroll
        for (int off = 16; off > 0; off >>= 1)
            lsum += __shfl_xor_sync(0xFFFFFFFFu, lsum, off);
        const float inv = 1.f / lsum;
        __syncwarp();

        float a0 = 0.f, a1 = 0.f;
        for (int kk = 0; kk < nk; kk++) {
            const float p = Pw[kk];
            a0 = fmaf(p, Vs[kk * KV_LD + lane],      a0);
            a1 = fmaf(p, Vs[kk * KV_LD + 32 + lane], a1);
        }
        a0 *= inv; a1 *= inv;
        if (qi == 0) { a0 = 0.f; a1 = 0.f; }

        const size_t o = ((size_t)bb * Sk + qi) * Dk + hh * DFk;
        bf16 h0 = __float2bfloat16(a0);
        bf16 h1 = __float2bfloat16(a1);
        g_chi[o + lane]      = h0;
        g_chi[o + lane + 32] = h1;
        g_clo[o + lane]      = __float2bfloat16(a0 - __bfloat162float(h0));
        g_clo[o + lane + 32] = __float2bfloat16(a1 - __bfloat162float(h1));
        __syncwarp();
    }
}

// ---------------- launch ----------------
extern "C" void kernel_launch(void* const* d_in, const int* in_sizes, int n_in,
                              void* d_out, int out_size)
{
    const float* q  = (const float*)d_in[0];
    const float* k  = (const float*)d_in[1];
    const float* v  = (const float*)d_in[2];
    const float* Wq = (const float*)d_in[3];
    const float* bq = (const float*)d_in[4];
    const float* Wk = (const float*)d_in[5];
    const float* bk = (const float*)d_in[6];
    const float* Wv = (const float*)d_in[7];
    const float* bv = (const float*)d_in[8];
    const float* Wo = (const float*)d_in[9];
    const float* bo = (const float*)d_in[10];
    float* out = (float*)d_out;

    const int nx4 = ROWS * Dk / 4;
    const int nw4 = Dk * Dk / 4;
    cvt_kernel<<<nx4 / 256, 256>>>(q,  0, nx4);
    cvt_kernel<<<nx4 / 256, 256>>>(k,  1, nx4);
    cvt_kernel<<<nx4 / 256, 256>>>(v,  2, nx4);
    cvt_kernel<<<nw4 / 256, 256>>>(Wq, 3, nw4);
    cvt_kernel<<<nw4 / 256, 256>>>(Wk, 4, nw4);
    cvt_kernel<<<nw4 / 256, 256>>>(Wv, 5, nw4);
    cvt_kernel<<<nw4 / 256, 256>>>(Wo, 6, nw4);

    cudaFuncSetAttribute(qkv_mma_kernel, cudaFuncAttributeMaxDynamicSharedMemorySize,
                         GEMM_SMEM);
    qkv_mma_kernel<<<dim3(Dk / 256, ROWS / 128, 3), 512, GEMM_SMEM>>>(bq, bk, bv);

    const int attn_smem = ATTN_SMEM_FLOATS * (int)sizeof(float);
    cudaFuncSetAttribute(attn_kernel, cudaFuncAttributeMaxDynamicSharedMemorySize,
                         attn_smem);
    attn_kernel<<<Bk * Hk, 256, attn_smem>>>();

    cudaFuncSetAttribute(out_mma_kernel, cudaFuncAttributeMaxDynamicSharedMemorySize,
                         GEMM_SMEM);
    out_mma_kernel<<<dim3(Dk / 256, ROWS / 128, 1), 512, GEMM_SMEM>>>(bo, out);
}

// round 6
// speedup vs baseline: 1.4585x; 1.3204x over previous
#include <cuda_runtime.h>
#include <cuda_bf16.h>
#include <math.h>
#include <stdint.h>

#define Bk 128
#define Sk 200
#define Dk 512
#define Hk 8
#define DFk 64
#define ROWS (Bk * Sk)          // 25600
#define SCALE 0.125f

typedef __nv_bfloat16 bf16;

// ---------------- device scratch ----------------
__device__ __align__(256) bf16 g_xhi[3][(size_t)ROWS * Dk];
__device__ __align__(256) bf16 g_xlo[3][(size_t)ROWS * Dk];
__device__ __align__(256) bf16 g_whi[4][(size_t)Dk * Dk];
__device__ __align__(256) bf16 g_wlo[4][(size_t)Dk * Dk];
__device__ __align__(256) bf16 g_Qh[(size_t)ROWS * Dk];   // [bh][s][64]
__device__ __align__(256) bf16 g_Ql[(size_t)ROWS * Dk];
__device__ __align__(256) bf16 g_Kh[(size_t)ROWS * Dk];
__device__ __align__(256) bf16 g_Kl[(size_t)ROWS * Dk];
__device__ __align__(256) bf16 g_Vh[(size_t)ROWS * Dk];   // [bh][df][s]
__device__ __align__(256) bf16 g_Vl[(size_t)ROWS * Dk];
__device__ __align__(256) bf16 g_chi[(size_t)ROWS * Dk];
__device__ __align__(256) bf16 g_clo[(size_t)ROWS * Dk];

// ---------------- helpers ----------------
#define MMA16816(d, a, b)                                                      \
    asm volatile(                                                              \
        "mma.sync.aligned.m16n8k16.row.col.f32.bf16.bf16.f32 "                 \
        "{%0,%1,%2,%3}, {%4,%5,%6,%7}, {%8,%9}, {%0,%1,%2,%3};"                \
        : "+f"((d)[0]), "+f"((d)[1]), "+f"((d)[2]), "+f"((d)[3])               \
        : "r"((a)[0]), "r"((a)[1]), "r"((a)[2]), "r"((a)[3]),                  \
          "r"((b)[0]), "r"((b)[1]))

static __device__ __forceinline__ void cp_async16(uint32_t saddr, const void* gaddr) {
    asm volatile("cp.async.cg.shared.global [%0], [%1], 16;"
                 :: "r"(saddr), "l"(gaddr));
}
static __device__ __forceinline__ void cp_commit() {
    asm volatile("cp.async.commit_group;" ::: "memory");
}
template <int N>
static __device__ __forceinline__ void cp_wait() {
    asm volatile("cp.async.wait_group %0;" :: "n"(N) : "memory");
}
static __device__ __forceinline__ uint32_t packbf(float lo, float hi) {
    uint32_t r;
    asm("cvt.rn.bf16x2.f32 %0, %1, %2;" : "=r"(r) : "f"(hi), "f"(lo));
    return r;
}
static __device__ __forceinline__ float fast_exp(float x) {
    x = fmaxf(x, -87.0f);
    float t = fmaf(x, 1.4426950408889634f, 12582912.0f);
    float f = fmaf(x, 1.4426950408889634f, -(t - 12582912.0f));
    float z = f * 0.6931471805599453f;
    float r = fmaf(0.0013888889f, z, 0.0083333333f);
    r = fmaf(r, z, 0.041666667f);
    r = fmaf(r, z, 0.16666667f);
    r = fmaf(r, z, 0.5f);
    r = fmaf(r, z, 1.0f);
    r = fmaf(r, z, 1.0f);
    return r * __int_as_float((__float_as_int(t) + (127 - 0x4B400000)) << 23);
}
static __device__ __forceinline__ void splitpack(float p0, float p1,
                                                 uint32_t& hi, uint32_t& lo) {
    float h0 = __bfloat162float(__float2bfloat16(p0));
    float h1 = __bfloat162float(__float2bfloat16(p1));
    hi = packbf(h0, h1);
    lo = packbf(p0 - h0, p1 - h1);
}

// ---------------- GEMM: 512 threads, CTA 128x256, BK=32, 3-split ----------------
#define BKC 32
#define NCH (Dk / BKC)
#define SA_HI 0
#define SA_LO 10240
#define SB_HI 20480
#define SB_LO 40960
#define STG_B 61440
#define GEMM_SMEM (2 * STG_B)

static __device__ __forceinline__ void load_chunk(
    char* stage, const bf16* __restrict__ Ah, const bf16* __restrict__ Al,
    const bf16* __restrict__ Bh, const bf16* __restrict__ Bl, int k0)
{
    const int tid = threadIdx.x;
    uint32_t sbase = (uint32_t)__cvta_generic_to_shared(stage);
#pragma unroll
    for (int j = 0; j < 6; j++) {
        const int idx = tid + j * 512;
        if (idx < 1024) {
            const int sp = idx >> 9;
            const int w  = idx & 511;
            const int r  = w >> 2;
            const int c  = w & 3;
            cp_async16(sbase + (sp ? SA_LO : SA_HI) + r * 80 + c * 16,
                       (sp ? Al : Ah) + (size_t)r * Dk + k0 + c * 8);
        } else {
            const int t  = idx - 1024;
            const int sp = t >> 10;
            const int w  = t & 1023;
            const int r  = w >> 2;
            const int c  = w & 3;
            cp_async16(sbase + (sp ? SB_LO : SB_HI) + r * 80 + c * 16,
                       (sp ? Bl : Bh) + (size_t)r * Dk + k0 + c * 8);
        }
    }
}

struct WAcc { float v[4][4][4]; };

static __device__ __forceinline__ void mma_mainloop(
    const bf16* __restrict__ Ahi, const bf16* __restrict__ Alo,
    const bf16* __restrict__ Bhi, const bf16* __restrict__ Blo,
    int m0, int n0, char* smem, WAcc& acc)
{
    const int tid   = threadIdx.x;
    const int wid   = tid >> 5;
    const int lane  = tid & 31;
    const int warpM = wid >> 3;
    const int warpN = wid & 7;
    const int g     = lane >> 2;
    const int q     = lane & 3;

    const bf16* Ah = Ahi + (size_t)m0 * Dk;
    const bf16* Al = Alo + (size_t)m0 * Dk;
    const bf16* Bh = Bhi + (size_t)n0 * Dk;
    const bf16* Bl = Blo + (size_t)n0 * Dk;

    load_chunk(smem, Ah, Al, Bh, Bl, 0);
    cp_commit();

    for (int c = 0; c < NCH; c++) {
        if (c + 1 < NCH) {
            load_chunk(smem + ((c + 1) & 1) * STG_B, Ah, Al, Bh, Bl, (c + 1) * BKC);
            cp_commit();
            cp_wait<1>();
        } else {
            cp_wait<0>();
        }
        __syncthreads();

        const char* stg = smem + (c & 1) * STG_B;
#pragma unroll
        for (int kh = 0; kh < 2; kh++) {
            uint32_t bh_[4][2], bl_[4][2];
#pragma unroll
            for (int nf = 0; nf < 4; nf++) {
                const int n = warpN * 32 + nf * 8 + g;
                const int o = n * 80 + kh * 32 + q * 4;
                bh_[nf][0] = *(const uint32_t*)(stg + SB_HI + o);
                bh_[nf][1] = *(const uint32_t*)(stg + SB_HI + o + 16);
                bl_[nf][0] = *(const uint32_t*)(stg + SB_LO + o);
                bl_[nf][1] = *(const uint32_t*)(stg + SB_LO + o + 16);
            }
#pragma unroll
            for (int mf = 0; mf < 4; mf++) {
                const int r = warpM * 64 + mf * 16 + g;
                const int o = r * 80 + kh * 32 + q * 4;
                uint32_t ah[4], al[4];
                ah[0] = *(const uint32_t*)(stg + SA_HI + o);
                ah[1] = *(const uint32_t*)(stg + SA_HI + o + 640);
                ah[2] = *(const uint32_t*)(stg + SA_HI + o + 16);
                ah[3] = *(const uint32_t*)(stg + SA_HI + o + 656);
                al[0] = *(const uint32_t*)(stg + SA_LO + o);
                al[1] = *(const uint32_t*)(stg + SA_LO + o + 640);
                al[2] = *(const uint32_t*)(stg + SA_LO + o + 16);
                al[3] = *(const uint32_t*)(stg + SA_LO + o + 656);
#pragma unroll
                for (int nf = 0; nf < 4; nf++) {
                    MMA16816(acc.v[mf][nf], ah, bh_[nf]);
                    MMA16816(acc.v[mf][nf], ah, bl_[nf]);
                    MMA16816(acc.v[mf][nf], al, bh_[nf]);
                }
            }
        }
        __syncthreads();
    }
}

// ---------------- QKV projection: bf16 hi/lo epilogue ----------------
__global__ __launch_bounds__(512, 1)
void qkv_mma_kernel(const float* __restrict__ bq, const float* __restrict__ bk,
                    const float* __restrict__ bv)
{
    extern __shared__ char smem[];
    const int z  = blockIdx.z;
    const int m0 = blockIdx.y * 128;
    const int n0 = blockIdx.x * 256;

    WAcc acc;
#pragma unroll
    for (int a = 0; a < 4; a++)
#pragma unroll
        for (int b = 0; b < 4; b++)
#pragma unroll
            for (int cc = 0; cc < 4; cc++) acc.v[a][b][cc] = 0.f;

    mma_mainloop(g_xhi[z], g_xlo[z], g_whi[z], g_wlo[z], m0, n0, smem, acc);

    const float* bias = (z == 0) ? bq : (z == 1) ? bk : bv;
    bf16* oh = (z == 0) ? g_Qh : (z == 1) ? g_Kh : g_Vh;
    bf16* ol = (z == 0) ? g_Ql : (z == 1) ? g_Kl : g_Vl;

    const int lane  = threadIdx.x & 31;
    const int wid   = threadIdx.x >> 5;
    const int warpM = wid >> 3, warpN = wid & 7;
    const int g     = lane >> 2, q = lane & 3;

#pragma unroll
    for (int mf = 0; mf < 4; mf++) {
#pragma unroll
        for (int half = 0; half < 2; half++) {
            const int m  = m0 + warpM * 64 + mf * 16 + g + half * 8;
            const int bb = m / Sk;
            const int ss = m - bb * Sk;
#pragma unroll
            for (int nf = 0; nf < 4; nf++) {
                const int n  = n0 + warpN * 32 + nf * 8 + q * 2;
                const int hh = n >> 6;
                const int df = n & 63;
                float v0 = acc.v[mf][nf][half * 2 + 0] + bias[n];
                float v1 = acc.v[mf][nf][half * 2 + 1] + bias[n + 1];
                bf16 h0 = __float2bfloat16(v0);
                bf16 h1 = __float2bfloat16(v1);
                bf16 l0 = __float2bfloat16(v0 - __bfloat162float(h0));
                bf16 l1 = __float2bfloat16(v1 - __bfloat162float(h1));
                const size_t bh = (size_t)bb * Hk + hh;
                if (z < 2) {
                    const size_t o = (bh * Sk + ss) * DFk + df;
                    *(__nv_bfloat162*)&oh[o] = __halves2bfloat162(h0, h1);
                    *(__nv_bfloat162*)&ol[o] = __halves2bfloat162(l0, l1);
                } else {
                    const size_t o = (bh * DFk + df) * Sk + ss;
                    oh[o] = h0; oh[o + Sk] = h1;
                    ol[o] = l0; ol[o + Sk] = l1;
                }
            }
        }
    }
}

// ---------------- output projection ----------------
__global__ __launch_bounds__(512, 1)
void out_mma_kernel(const float* __restrict__ bo, float* __restrict__ out)
{
    extern __shared__ char smem[];
    const int m0 = blockIdx.y * 128;
    const int n0 = blockIdx.x * 256;

    WAcc acc;
#pragma unroll
    for (int a = 0; a < 4; a++)
#pragma unroll
        for (int b = 0; b < 4; b++)
#pragma unroll
            for (int cc = 0; cc < 4; cc++) acc.v[a][b][cc] = 0.f;

    mma_mainloop(g_chi, g_clo, g_whi[3], g_wlo[3], m0, n0, smem, acc);

    const int lane  = threadIdx.x & 31;
    const int wid   = threadIdx.x >> 5;
    const int warpM = wid >> 3, warpN = wid & 7;
    const int g     = lane >> 2, q = lane & 3;

#pragma unroll
    for (int mf = 0; mf < 4; mf++) {
#pragma unroll
        for (int half = 0; half < 2; half++) {
            const int m = m0 + warpM * 64 + mf * 16 + g + half * 8;
#pragma unroll
            for (int nf = 0; nf < 4; nf++) {
                const int n = n0 + warpN * 32 + nf * 8 + q * 2;
                float2 v;
                v.x = acc.v[mf][nf][half * 2 + 0] + bo[n];
                v.y = acc.v[mf][nf][half * 2 + 1] + bo[n + 1];
                *(float2*)(out + (size_t)m * Dk + n) = v;
            }
        }
    }
}

// ---------------- fp32 -> bf16 hi/lo split ----------------
__global__ void cvt_kernel(const float* __restrict__ x, int which, int n4)
{
    const int i = blockIdx.x * blockDim.x + threadIdx.x;
    if (i >= n4) return;
    bf16* hi = (which < 3) ? g_xhi[which] : g_whi[which - 3];
    bf16* lo = (which < 3) ? g_xlo[which] : g_wlo[which - 3];
    float4 v = ((const float4*)x)[i];
    bf16 h0 = __float2bfloat16(v.x), h1 = __float2bfloat16(v.y);
    bf16 h2 = __float2bfloat16(v.z), h3 = __float2bfloat16(v.w);
    bf16 l0 = __float2bfloat16(v.x - __bfloat162float(h0));
    bf16 l1 = __float2bfloat16(v.y - __bfloat162float(h1));
    bf16 l2 = __float2bfloat16(v.z - __bfloat162float(h2));
    bf16 l3 = __float2bfloat16(v.w - __bfloat162float(h3));
    ((__nv_bfloat162*)hi)[2 * i]     = __halves2bfloat162(h0, h1);
    ((__nv_bfloat162*)hi)[2 * i + 1] = __halves2bfloat162(h2, h3);
    ((__nv_bfloat162*)lo)[2 * i]     = __halves2bfloat162(l0, l1);
    ((__nv_bfloat162*)lo)[2 * i + 1] = __halves2bfloat162(l2, l3);
}

// ---------------- tensor-core attention ----------------
// smem elems: Qh 0, Ql 9216 (128x72); Kh 18432, Kl 33408 (stride 72);
//             VhT 48384, VlT 62208 (64x216). Total 76032 elems = 152064 B.
#define ATTN_SMEM 152064

template <int QB>
__global__ __launch_bounds__(256, 1)
void attn_mma_kernel()
{
    constexpr int NF  = (QB == 0) ? 16 : 25;   // key n-frags (8 keys each)
    constexpr int KR  = (QB == 0) ? 128 : 200; // key rows to stage
    constexpr int NKC = (NF + 1) / 2;          // P k-chunks (k16)
    constexpr int VQ  = (QB == 0) ? 128 : 72;  // valid query rows
    constexpr int VC  = (QB == 0) ? 16 : 26;   // V^T col chunks of 8

    extern __shared__ bf16 smb[];
    const int bh  = blockIdx.x;
    const int tid = threadIdx.x;
    uint32_t sb = (uint32_t)__cvta_generic_to_shared(smb);

    for (int u = tid; u < 2 * 128 * 8; u += 256) {
        int sp = u >> 10, w2 = u & 1023, r = w2 >> 3, c = w2 & 7;
        int rr = min(r, VQ - 1);
        cp_async16(sb + (uint32_t)((sp ? 9216 : 0) + r * 72 + c * 8) * 2,
                   (sp ? g_Ql : g_Qh) + ((size_t)bh * Sk + QB * 128 + rr) * DFk + c * 8);
    }
    for (int u = tid; u < 2 * KR * 8; u += 256) {
        int sp = (u >= KR * 8), w2 = u - sp * KR * 8, r = w2 >> 3, c = w2 & 7;
        cp_async16(sb + (uint32_t)((sp ? 33408 : 18432) + r * 72 + c * 8) * 2,
                   (sp ? g_Kl : g_Kh) + ((size_t)bh * Sk + r) * DFk + c * 8);
    }
    for (int u = tid; u < 2 * 64 * VC; u += 256) {
        int sp = (u >= 64 * VC), w2 = u - sp * 64 * VC, r = w2 / VC, c = w2 - r * VC;
        int cc = min(c, 24);
        cp_async16(sb + (uint32_t)((sp ? 62208 : 48384) + r * 216 + c * 8) * 2,
                   (sp ? g_Vl : g_Vh) + ((size_t)bh * DFk + r) * Sk + cc * 8);
    }
    cp_commit();
    cp_wait<0>();
    __syncthreads();

    const int w = tid >> 5, lane = tid & 31, g = lane >> 2, q = lane & 3;
    if (QB == 1 && w >= 5) return;
    const int qr0 = QB * 128 + w * 16 + g;
    const int qr1 = qr0 + 8;
    const int NFW = (QB == 0) ? (2 * w + 2) : min(NF, 18 + 2 * w);
    const int KCW = (NFW + 1) / 2;

    // hoist Q a-frags (hi+lo, 4 k16 chunks over DF=64)
    uint32_t qah[4][4], qal[4][4];
#pragma unroll
    for (int kc = 0; kc < 4; kc++) {
        const int r0  = w * 16 + g;
        const int col = 16 * kc + 2 * q;
        qah[kc][0] = *(const uint32_t*)&smb[r0 * 72 + col];
        qah[kc][1] = *(const uint32_t*)&smb[(r0 + 8) * 72 + col];
        qah[kc][2] = *(const uint32_t*)&smb[r0 * 72 + col + 8];
        qah[kc][3] = *(const uint32_t*)&smb[(r0 + 8) * 72 + col + 8];
        qal[kc][0] = *(const uint32_t*)&smb[9216 + r0 * 72 + col];
        qal[kc][1] = *(const uint32_t*)&smb[9216 + (r0 + 8) * 72 + col];
        qal[kc][2] = *(const uint32_t*)&smb[9216 + r0 * 72 + col + 8];
        qal[kc][3] = *(const uint32_t*)&smb[9216 + (r0 + 8) * 72 + col + 8];
    }

    // QK^T (3-split) + causal mask + row max
    float sc[NF][4];
    float mx0 = -1e30f, mx1 = -1e30f;
#pragma unroll
    for (int nf = 0; nf < NF; nf++) {
        sc[nf][0] = sc[nf][1] = sc[nf][2] = sc[nf][3] = 0.f;
        if (nf < NFW) {
#pragma unroll
            for (int kc = 0; kc < 4; kc++) {
                const int o = (8 * nf + g) * 72 + 16 * kc + 2 * q;
                uint32_t kb[2], kl2[2];
                kb[0]  = *(const uint32_t*)&smb[18432 + o];
                kb[1]  = *(const uint32_t*)&smb[18432 + o + 8];
                kl2[0] = *(const uint32_t*)&smb[33408 + o];
                kl2[1] = *(const uint32_t*)&smb[33408 + o + 8];
                MMA16816(sc[nf], qah[kc], kb);
                MMA16816(sc[nf], qah[kc], kl2);
                MMA16816(sc[nf], qal[kc], kb);
            }
            const int k0 = 8 * nf + 2 * q;
            sc[nf][0] = (k0     <= qr0) ? sc[nf][0] * SCALE : -1e30f;
            sc[nf][1] = (k0 + 1 <= qr0) ? sc[nf][1] * SCALE : -1e30f;
            sc[nf][2] = (k0     <= qr1) ? sc[nf][2] * SCALE : -1e30f;
            sc[nf][3] = (k0 + 1 <= qr1) ? sc[nf][3] * SCALE : -1e30f;
            mx0 = fmaxf(mx0, fmaxf(sc[nf][0], sc[nf][1]));
            mx1 = fmaxf(mx1, fmaxf(sc[nf][2], sc[nf][3]));
        }
    }
    mx0 = fmaxf(mx0, __shfl_xor_sync(0xFFFFFFFFu, mx0, 1));
    mx0 = fmaxf(mx0, __shfl_xor_sync(0xFFFFFFFFu, mx0, 2));
    mx1 = fmaxf(mx1, __shfl_xor_sync(0xFFFFFFFFu, mx1, 1));
    mx1 = fmaxf(mx1, __shfl_xor_sync(0xFFFFFFFFu, mx1, 2));

    // exp + row sums
    float sum0 = 0.f, sum1 = 0.f;
#pragma unroll
    for (int nf = 0; nf < NF; nf++) {
        if (nf < NFW) {
            sc[nf][0] = fast_exp(sc[nf][0] - mx0);
            sc[nf][1] = fast_exp(sc[nf][1] - mx0);
            sc[nf][2] = fast_exp(sc[nf][2] - mx1);
            sc[nf][3] = fast_exp(sc[nf][3] - mx1);
            sum0 += sc[nf][0] + sc[nf][1];
            sum1 += sc[nf][2] + sc[nf][3];
        }
    }
    sum0 += __shfl_xor_sync(0xFFFFFFFFu, sum0, 1);
    sum0 += __shfl_xor_sync(0xFFFFFFFFu, sum0, 2);
    sum1 += __shfl_xor_sync(0xFFFFFFFFu, sum1, 1);
    sum1 += __shfl_xor_sync(0xFFFFFFFFu, sum1, 2);
    float inv0 = (qr0 == 0) ? 0.f : 1.f / fmaxf(sum0, 1e-37f);   // zero_pad row 0
    float inv1 = 1.f / fmaxf(sum1, 1e-37f);

    // P·V (3-split), P frags packed register-locally from score frags
    float oa[8][4];
#pragma unroll
    for (int nv = 0; nv < 8; nv++)
        oa[nv][0] = oa[nv][1] = oa[nv][2] = oa[nv][3] = 0.f;

#pragma unroll
    for (int kc = 0; kc < NKC; kc++) {
        if (kc < KCW) {
            uint32_t ph[4], pl[4];
            splitpack(sc[2 * kc][0] * inv0, sc[2 * kc][1] * inv0, ph[0], pl[0]);
            splitpack(sc[2 * kc][2] * inv1, sc[2 * kc][3] * inv1, ph[1], pl[1]);
            if (2 * kc + 1 < NF) {
                splitpack(sc[2 * kc + 1][0] * inv0, sc[2 * kc + 1][1] * inv0, ph[2], pl[2]);
                splitpack(sc[2 * kc + 1][2] * inv1, sc[2 * kc + 1][3] * inv1, ph[3], pl[3]);
            } else {
                ph[2] = ph[3] = pl[2] = pl[3] = 0u;
            }
#pragma unroll
            for (int nv = 0; nv < 8; nv++) {
                const int o = (8 * nv + g) * 216 + 16 * kc + 2 * q;
                uint32_t vb[2], vl2[2];
                vb[0]  = *(const uint32_t*)&smb[48384 + o];
                vb[1]  = *(const uint32_t*)&smb[48384 + o + 8];
                vl2[0] = *(const uint32_t*)&smb[62208 + o];
                vl2[1] = *(const uint32_t*)&smb[62208 + o + 8];
                MMA16816(oa[nv], ph, vb);
                MMA16816(oa[nv], ph, vl2);
                MMA16816(oa[nv], pl, vb);
            }
        }
    }

    // store ctx bf16 hi/lo
    const int bbb = bh >> 3, hh = bh & 7;
#pragma unroll
    for (int nv = 0; nv < 8; nv++) {
        const int df = 8 * nv + 2 * q;
        {
            const size_t o = ((size_t)bbb * Sk + qr0) * Dk + hh * 64 + df;
            bf16 a = __float2bfloat16(oa[nv][0]);
            bf16 b = __float2bfloat16(oa[nv][1]);
            *(__nv_bfloat162*)&g_chi[o] = __halves2bfloat162(a, b);
            *(__nv_bfloat162*)&g_clo[o] = __halves2bfloat162(
                __float2bfloat16(oa[nv][0] - __bfloat162float(a)),
                __float2bfloat16(oa[nv][1] - __bfloat162float(b)));
        }
        if (qr1 < Sk) {
            const size_t o = ((size_t)bbb * Sk + qr1) * Dk + hh * 64 + df;
            bf16 a = __float2bfloat16(oa[nv][2]);
            bf16 b = __float2bfloat16(oa[nv][3]);
            *(__nv_bfloat162*)&g_chi[o] = __halves2bfloat162(a, b);
            *(__nv_bfloat162*)&g_clo[o] = __halves2bfloat162(
                __float2bfloat16(oa[nv][2] - __bfloat162float(a)),
                __float2bfloat16(oa[nv][3] - __bfloat162float(b)));
        }
    }
}

// ---------------- launch ----------------
extern "C" void kernel_launch(void* const* d_in, const int* in_sizes, int n_in,
                              void* d_out, int out_size)
{
    const float* q  = (const float*)d_in[0];
    const float* k  = (const float*)d_in[1];
    const float* v  = (const float*)d_in[2];
    const float* Wq = (const float*)d_in[3];
    const float* bq = (const float*)d_in[4];
    const float* Wk = (const float*)d_in[5];
    const float* bk = (const float*)d_in[6];
    const float* Wv = (const float*)d_in[7];
    const float* bv = (const float*)d_in[8];
    const float* Wo = (const float*)d_in[9];
    const float* bo = (const float*)d_in[10];
    float* out = (float*)d_out;

    const int nx4 = ROWS * Dk / 4;
    const int nw4 = Dk * Dk / 4;
    cvt_kernel<<<nx4 / 256, 256>>>(q,  0, nx4);
    cvt_kernel<<<nx4 / 256, 256>>>(k,  1, nx4);
    cvt_kernel<<<nx4 / 256, 256>>>(v,  2, nx4);
    cvt_kernel<<<nw4 / 256, 256>>>(Wq, 3, nw4);
    cvt_kernel<<<nw4 / 256, 256>>>(Wk, 4, nw4);
    cvt_kernel<<<nw4 / 256, 256>>>(Wv, 5, nw4);
    cvt_kernel<<<nw4 / 256, 256>>>(Wo, 6, nw4);

    cudaFuncSetAttribute(qkv_mma_kernel, cudaFuncAttributeMaxDynamicSharedMemorySize,
                         GEMM_SMEM);
    qkv_mma_kernel<<<dim3(Dk / 256, ROWS / 128, 3), 512, GEMM_SMEM>>>(bq, bk, bv);

    cudaFuncSetAttribute(attn_mma_kernel<0>, cudaFuncAttributeMaxDynamicSharedMemorySize,
                         ATTN_SMEM);
    cudaFuncSetAttribute(attn_mma_kernel<1>, cudaFuncAttributeMaxDynamicSharedMemorySize,
                         ATTN_SMEM);
    attn_mma_kernel<0><<<Bk * Hk, 256, ATTN_SMEM>>>();
    attn_mma_kernel<1><<<Bk * Hk, 256, ATTN_SMEM>>>();

    cudaFuncSetAttribute(out_mma_kernel, cudaFuncAttributeMaxDynamicSharedMemorySize,
                         GEMM_SMEM);
    out_mma_kernel<<<dim3(Dk / 256, ROWS / 128, 1), 512, GEMM_SMEM>>>(bo, out);
}

// round 7
// speedup vs baseline: 1.4973x; 1.0266x over previous
#include <cuda_runtime.h>
#include <cuda_bf16.h>
#include <math.h>
#include <stdint.h>

#define Bk 128
#define Sk 200
#define Dk 512
#define Hk 8
#define DFk 64
#define ROWS (Bk * Sk)          // 25600
#define SCALE 0.125f

typedef __nv_bfloat16 bf16;

// ---------------- device scratch ----------------
__device__ __align__(256) bf16 g_xhi[3][(size_t)ROWS * Dk];
__device__ __align__(256) bf16 g_xlo[3][(size_t)ROWS * Dk];
__device__ __align__(256) bf16 g_whi[4][(size_t)Dk * Dk];
__device__ __align__(256) bf16 g_wlo[4][(size_t)Dk * Dk];
__device__ __align__(256) bf16 g_Qh[(size_t)ROWS * Dk];   // [bh][s][64]
__device__ __align__(256) bf16 g_Ql[(size_t)ROWS * Dk];
__device__ __align__(256) bf16 g_Kh[(size_t)ROWS * Dk];
__device__ __align__(256) bf16 g_Kl[(size_t)ROWS * Dk];
__device__ __align__(256) bf16 g_Vh[(size_t)ROWS * Dk];   // [bh][df][s]
__device__ __align__(256) bf16 g_Vl[(size_t)ROWS * Dk];
__device__ __align__(256) bf16 g_chi[(size_t)ROWS * Dk];
__device__ __align__(256) bf16 g_clo[(size_t)ROWS * Dk];

// ---------------- helpers ----------------
#define MMA16816(d, a, b)                                                      \
    asm volatile(                                                              \
        "mma.sync.aligned.m16n8k16.row.col.f32.bf16.bf16.f32 "                 \
        "{%0,%1,%2,%3}, {%4,%5,%6,%7}, {%8,%9}, {%0,%1,%2,%3};"                \
        : "+f"((d)[0]), "+f"((d)[1]), "+f"((d)[2]), "+f"((d)[3])               \
        : "r"((a)[0]), "r"((a)[1]), "r"((a)[2]), "r"((a)[3]),                  \
          "r"((b)[0]), "r"((b)[1]))

#define LDSM_X4(r0, r1, r2, r3, addr)                                          \
    asm volatile("ldmatrix.sync.aligned.m8n8.x4.shared.b16 {%0,%1,%2,%3}, [%4];" \
                 : "=r"(r0), "=r"(r1), "=r"(r2), "=r"(r3) : "r"(addr))

static __device__ __forceinline__ void cp_async16(uint32_t saddr, const void* gaddr) {
    asm volatile("cp.async.cg.shared.global [%0], [%1], 16;"
                 :: "r"(saddr), "l"(gaddr));
}
static __device__ __forceinline__ void cp_commit() {
    asm volatile("cp.async.commit_group;" ::: "memory");
}
template <int N>
static __device__ __forceinline__ void cp_wait() {
    asm volatile("cp.async.wait_group %0;" :: "n"(N) : "memory");
}
static __device__ __forceinline__ uint32_t packbf(float lo, float hi) {
    uint32_t r;
    asm("cvt.rn.bf16x2.f32 %0, %1, %2;" : "=r"(r) : "f"(hi), "f"(lo));
    return r;
}
static __device__ __forceinline__ float fast_exp(float x) {
    x = fmaxf(x, -87.0f);
    float t = fmaf(x, 1.4426950408889634f, 12582912.0f);
    float f = fmaf(x, 1.4426950408889634f, -(t - 12582912.0f));
    float z = f * 0.6931471805599453f;
    float r = fmaf(0.0013888889f, z, 0.0083333333f);
    r = fmaf(r, z, 0.041666667f);
    r = fmaf(r, z, 0.16666667f);
    r = fmaf(r, z, 0.5f);
    r = fmaf(r, z, 1.0f);
    r = fmaf(r, z, 1.0f);
    return r * __int_as_float((__float_as_int(t) + (127 - 0x4B400000)) << 23);
}
static __device__ __forceinline__ void splitpack(float p0, float p1,
                                                 uint32_t& hi, uint32_t& lo) {
    float h0 = __bfloat162float(__float2bfloat16(p0));
    float h1 = __bfloat162float(__float2bfloat16(p1));
    hi = packbf(h0, h1);
    lo = packbf(p0 - h0, p1 - h1);
}

// ---------------- GEMM: 512 threads, CTA 128x256, BK=32, 3-stage, ldmatrix ---
#define BKC 32
#define NCH (Dk / BKC)
#define SA_HI 0
#define SA_LO 10240
#define SB_HI 20480
#define SB_LO 40960
#define STG_B 61440
#define GEMM_SMEM (3 * STG_B)   // 184320

static __device__ __forceinline__ void load_chunk(
    char* stage, const bf16* __restrict__ Ah, const bf16* __restrict__ Al,
    const bf16* __restrict__ Bh, const bf16* __restrict__ Bl, int k0)
{
    const int tid = threadIdx.x;
    uint32_t sbase = (uint32_t)__cvta_generic_to_shared(stage);
#pragma unroll
    for (int j = 0; j < 6; j++) {
        const int idx = tid + j * 512;
        if (idx < 1024) {
            const int sp = idx >> 9;
            const int w  = idx & 511;
            const int r  = w >> 2;
            const int c  = w & 3;
            cp_async16(sbase + (sp ? SA_LO : SA_HI) + r * 80 + c * 16,
                       (sp ? Al : Ah) + (size_t)r * Dk + k0 + c * 8);
        } else {
            const int t  = idx - 1024;
            const int sp = t >> 10;
            const int w  = t & 1023;
            const int r  = w >> 2;
            const int c  = w & 3;
            cp_async16(sbase + (sp ? SB_LO : SB_HI) + r * 80 + c * 16,
                       (sp ? Bl : Bh) + (size_t)r * Dk + k0 + c * 8);
        }
    }
}

struct WAcc { float v[4][4][4]; };

static __device__ __forceinline__ void mma_mainloop(
    const bf16* __restrict__ Ahi, const bf16* __restrict__ Alo,
    const bf16* __restrict__ Bhi, const bf16* __restrict__ Blo,
    int m0, int n0, char* smem, WAcc& acc)
{
    const int tid   = threadIdx.x;
    const int wid   = tid >> 5;
    const int lane  = tid & 31;
    const int warpM = wid >> 3;
    const int warpN = wid & 7;
    const int lr    = lane & 7;
    const int lb3   = (lane >> 3) & 1;
    const int lb4   = (lane >> 4) & 1;

    // ldmatrix per-lane base offsets (bytes within a stage)
    const uint32_t abase = (uint32_t)((warpM * 64 + lr + lb3 * 8) * 80 + lb4 * 16);
    const uint32_t bbase = (uint32_t)((warpN * 32 + lr + lb4 * 8) * 80 + lb3 * 16);

    const bf16* Ah = Ahi + (size_t)m0 * Dk;
    const bf16* Al = Alo + (size_t)m0 * Dk;
    const bf16* Bh = Bhi + (size_t)n0 * Dk;
    const bf16* Bl = Blo + (size_t)n0 * Dk;

    uint32_t sbase = (uint32_t)__cvta_generic_to_shared(smem);

    load_chunk(smem, Ah, Al, Bh, Bl, 0);
    cp_commit();
    load_chunk(smem + STG_B, Ah, Al, Bh, Bl, BKC);
    cp_commit();

    int st = 0;   // stage of chunk c
    for (int c = 0; c < NCH; c++) {
        int stn = st + 2; if (stn >= 3) stn -= 3;
        if (c + 2 < NCH) {
            load_chunk(smem + stn * STG_B, Ah, Al, Bh, Bl, (c + 2) * BKC);
            cp_commit();
            cp_wait<2>();
        } else {
            cp_wait<0>();
        }
        __syncthreads();

        const uint32_t sg = sbase + st * STG_B;
#pragma unroll
        for (int kh = 0; kh < 2; kh++) {
            uint32_t bh_[4][2], bl_[4][2];
#pragma unroll
            for (int nfp = 0; nfp < 2; nfp++) {
                const uint32_t bo = sg + bbase + nfp * 1280 + kh * 32;
                LDSM_X4(bh_[2 * nfp][0], bh_[2 * nfp][1],
                        bh_[2 * nfp + 1][0], bh_[2 * nfp + 1][1], bo + SB_HI);
                LDSM_X4(bl_[2 * nfp][0], bl_[2 * nfp][1],
                        bl_[2 * nfp + 1][0], bl_[2 * nfp + 1][1], bo + SB_LO);
            }
#pragma unroll
            for (int mf = 0; mf < 4; mf++) {
                const uint32_t ao = sg + abase + mf * 1280 + kh * 32;
                uint32_t ah[4], al[4];
                LDSM_X4(ah[0], ah[1], ah[2], ah[3], ao + SA_HI);
                LDSM_X4(al[0], al[1], al[2], al[3], ao + SA_LO);
#pragma unroll
                for (int nf = 0; nf < 4; nf++) {
                    MMA16816(acc.v[mf][nf], ah, bh_[nf]);
                    MMA16816(acc.v[mf][nf], ah, bl_[nf]);
                    MMA16816(acc.v[mf][nf], al, bh_[nf]);
                }
            }
        }
        __syncthreads();
        st = st + 1; if (st >= 3) st -= 3;
    }
}

// ---------------- QKV projection: bf16 hi/lo epilogue ----------------
__global__ __launch_bounds__(512, 1)
void qkv_mma_kernel(const float* __restrict__ bq, const float* __restrict__ bk,
                    const float* __restrict__ bv)
{
    extern __shared__ char smem[];
    const int z  = blockIdx.z;
    const int m0 = blockIdx.y * 128;
    const int n0 = blockIdx.x * 256;

    WAcc acc;
#pragma unroll
    for (int a = 0; a < 4; a++)
#pragma unroll
        for (int b = 0; b < 4; b++)
#pragma unroll
            for (int cc = 0; cc < 4; cc++) acc.v[a][b][cc] = 0.f;

    mma_mainloop(g_xhi[z], g_xlo[z], g_whi[z], g_wlo[z], m0, n0, smem, acc);

    const float* bias = (z == 0) ? bq : (z == 1) ? bk : bv;
    bf16* oh = (z == 0) ? g_Qh : (z == 1) ? g_Kh : g_Vh;
    bf16* ol = (z == 0) ? g_Ql : (z == 1) ? g_Kl : g_Vl;

    const int lane  = threadIdx.x & 31;
    const int wid   = threadIdx.x >> 5;
    const int warpM = wid >> 3, warpN = wid & 7;
    const int g     = lane >> 2, q = lane & 3;

#pragma unroll
    for (int mf = 0; mf < 4; mf++) {
#pragma unroll
        for (int half = 0; half < 2; half++) {
            const int m  = m0 + warpM * 64 + mf * 16 + g + half * 8;
            const int bb = m / Sk;
            const int ss = m - bb * Sk;
#pragma unroll
            for (int nf = 0; nf < 4; nf++) {
                const int n  = n0 + warpN * 32 + nf * 8 + q * 2;
                const int hh = n >> 6;
                const int df = n & 63;
                float v0 = acc.v[mf][nf][half * 2 + 0] + bias[n];
                float v1 = acc.v[mf][nf][half * 2 + 1] + bias[n + 1];
                bf16 h0 = __float2bfloat16(v0);
                bf16 h1 = __float2bfloat16(v1);
                bf16 l0 = __float2bfloat16(v0 - __bfloat162float(h0));
                bf16 l1 = __float2bfloat16(v1 - __bfloat162float(h1));
                const size_t bh = (size_t)bb * Hk + hh;
                if (z < 2) {
                    const size_t o = (bh * Sk + ss) * DFk + df;
                    *(__nv_bfloat162*)&oh[o] = __halves2bfloat162(h0, h1);
                    *(__nv_bfloat162*)&ol[o] = __halves2bfloat162(l0, l1);
                } else {
                    const size_t o = (bh * DFk + df) * Sk + ss;
                    oh[o] = h0; oh[o + Sk] = h1;
                    ol[o] = l0; ol[o + Sk] = l1;
                }
            }
        }
    }
}

// ---------------- output projection ----------------
__global__ __launch_bounds__(512, 1)
void out_mma_kernel(const float* __restrict__ bo, float* __restrict__ out)
{
    extern __shared__ char smem[];
    const int m0 = blockIdx.y * 128;
    const int n0 = blockIdx.x * 256;

    WAcc acc;
#pragma unroll
    for (int a = 0; a < 4; a++)
#pragma unroll
        for (int b = 0; b < 4; b++)
#pragma unroll
            for (int cc = 0; cc < 4; cc++) acc.v[a][b][cc] = 0.f;

    mma_mainloop(g_chi, g_clo, g_whi[3], g_wlo[3], m0, n0, smem, acc);

    const int lane  = threadIdx.x & 31;
    const int wid   = threadIdx.x >> 5;
    const int warpM = wid >> 3, warpN = wid & 7;
    const int g     = lane >> 2, q = lane & 3;

#pragma unroll
    for (int mf = 0; mf < 4; mf++) {
#pragma unroll
        for (int half = 0; half < 2; half++) {
            const int m = m0 + warpM * 64 + mf * 16 + g + half * 8;
#pragma unroll
            for (int nf = 0; nf < 4; nf++) {
                const int n = n0 + warpN * 32 + nf * 8 + q * 2;
                float2 v;
                v.x = acc.v[mf][nf][half * 2 + 0] + bo[n];
                v.y = acc.v[mf][nf][half * 2 + 1] + bo[n + 1];
                *(float2*)(out + (size_t)m * Dk + n) = v;
            }
        }
    }
}

// ---------------- fp32 -> bf16 hi/lo split ----------------
__global__ void cvt_kernel(const float* __restrict__ x, int which, int n4)
{
    const int i = blockIdx.x * blockDim.x + threadIdx.x;
    if (i >= n4) return;
    bf16* hi = (which < 3) ? g_xhi[which] : g_whi[which - 3];
    bf16* lo = (which < 3) ? g_xlo[which] : g_wlo[which - 3];
    float4 v = ((const float4*)x)[i];
    bf16 h0 = __float2bfloat16(v.x), h1 = __float2bfloat16(v.y);
    bf16 h2 = __float2bfloat16(v.z), h3 = __float2bfloat16(v.w);
    bf16 l0 = __float2bfloat16(v.x - __bfloat162float(h0));
    bf16 l1 = __float2bfloat16(v.y - __bfloat162float(h1));
    bf16 l2 = __float2bfloat16(v.z - __bfloat162float(h2));
    bf16 l3 = __float2bfloat16(v.w - __bfloat162float(h3));
    ((__nv_bfloat162*)hi)[2 * i]     = __halves2bfloat162(h0, h1);
    ((__nv_bfloat162*)hi)[2 * i + 1] = __halves2bfloat162(h2, h3);
    ((__nv_bfloat162*)lo)[2 * i]     = __halves2bfloat162(l0, l1);
    ((__nv_bfloat162*)lo)[2 * i + 1] = __halves2bfloat162(l2, l3);
}

// ---------------- tensor-core attention (unchanged from R6) ----------------
#define ATTN_SMEM 152064

template <int QB>
__global__ __launch_bounds__(256, 1)
void attn_mma_kernel()
{
    constexpr int NF  = (QB == 0) ? 16 : 25;
    constexpr int KR  = (QB == 0) ? 128 : 200;
    constexpr int NKC = (NF + 1) / 2;
    constexpr int VQ  = (QB == 0) ? 128 : 72;
    constexpr int VC  = (QB == 0) ? 16 : 26;

    extern __shared__ bf16 smb[];
    const int bh  = blockIdx.x;
    const int tid = threadIdx.x;
    uint32_t sb = (uint32_t)__cvta_generic_to_shared(smb);

    for (int u = tid; u < 2 * 128 * 8; u += 256) {
        int sp = u >> 10, w2 = u & 1023, r = w2 >> 3, c = w2 & 7;
        int rr = min(r, VQ - 1);
        cp_async16(sb + (uint32_t)((sp ? 9216 : 0) + r * 72 + c * 8) * 2,
                   (sp ? g_Ql : g_Qh) + ((size_t)bh * Sk + QB * 128 + rr) * DFk + c * 8);
    }
    for (int u = tid; u < 2 * KR * 8; u += 256) {
        int sp = (u >= KR * 8), w2 = u - sp * KR * 8, r = w2 >> 3, c = w2 & 7;
        cp_async16(sb + (uint32_t)((sp ? 33408 : 18432) + r * 72 + c * 8) * 2,
                   (sp ? g_Kl : g_Kh) + ((size_t)bh * Sk + r) * DFk + c * 8);
    }
    for (int u = tid; u < 2 * 64 * VC; u += 256) {
        int sp = (u >= 64 * VC), w2 = u - sp * 64 * VC, r = w2 / VC, c = w2 - r * VC;
        int cc = min(c, 24);
        cp_async16(sb + (uint32_t)((sp ? 62208 : 48384) + r * 216 + c * 8) * 2,
                   (sp ? g_Vl : g_Vh) + ((size_t)bh * DFk + r) * Sk + cc * 8);
    }
    cp_commit();
    cp_wait<0>();
    __syncthreads();

    const int w = tid >> 5, lane = tid & 31, g = lane >> 2, q = lane & 3;
    if (QB == 1 && w >= 5) return;
    const int qr0 = QB * 128 + w * 16 + g;
    const int qr1 = qr0 + 8;
    const int NFW = (QB == 0) ? (2 * w + 2) : min(NF, 18 + 2 * w);
    const int KCW = (NFW + 1) / 2;

    uint32_t qah[4][4], qal[4][4];
#pragma unroll
    for (int kc = 0; kc < 4; kc++) {
        const int r0  = w * 16 + g;
        const int col = 16 * kc + 2 * q;
        qah[kc][0] = *(const uint32_t*)&smb[r0 * 72 + col];
        qah[kc][1] = *(const uint32_t*)&smb[(r0 + 8) * 72 + col];
        qah[kc][2] = *(const uint32_t*)&smb[r0 * 72 + col + 8];
        qah[kc][3] = *(const uint32_t*)&smb[(r0 + 8) * 72 + col + 8];
        qal[kc][0] = *(const uint32_t*)&smb[9216 + r0 * 72 + col];
        qal[kc][1] = *(const uint32_t*)&smb[9216 + (r0 + 8) * 72 + col];
        qal[kc][2] = *(const uint32_t*)&smb[9216 + r0 * 72 + col + 8];
        qal[kc][3] = *(const uint32_t*)&smb[9216 + (r0 + 8) * 72 + col + 8];
    }

    float sc[NF][4];
    float mx0 = -1e30f, mx1 = -1e30f;
#pragma unroll
    for (int nf = 0; nf < NF; nf++) {
        sc[nf][0] = sc[nf][1] = sc[nf][2] = sc[nf][3] = 0.f;
        if (nf < NFW) {
#pragma unroll
            for (int kc = 0; kc < 4; kc++) {
                const int o = (8 * nf + g) * 72 + 16 * kc + 2 * q;
                uint32_t kb[2], kl2[2];
                kb[0]  = *(const uint32_t*)&smb[18432 + o];
                kb[1]  = *(const uint32_t*)&smb[18432 + o + 8];
                kl2[0] = *(const uint32_t*)&smb[33408 + o];
                kl2[1] = *(const uint32_t*)&smb[33408 + o + 8];
                MMA16816(sc[nf], qah[kc], kb);
                MMA16816(sc[nf], qah[kc], kl2);
                MMA16816(sc[nf], qal[kc], kb);
            }
            const int k0 = 8 * nf + 2 * q;
            sc[nf][0] = (k0     <= qr0) ? sc[nf][0] * SCALE : -1e30f;
            sc[nf][1] = (k0 + 1 <= qr0) ? sc[nf][1] * SCALE : -1e30f;
            sc[nf][2] = (k0     <= qr1) ? sc[nf][2] * SCALE : -1e30f;
            sc[nf][3] = (k0 + 1 <= qr1) ? sc[nf][3] * SCALE : -1e30f;
            mx0 = fmaxf(mx0, fmaxf(sc[nf][0], sc[nf][1]));
            mx1 = fmaxf(mx1, fmaxf(sc[nf][2], sc[nf][3]));
        }
    }
    mx0 = fmaxf(mx0, __shfl_xor_sync(0xFFFFFFFFu, mx0, 1));
    mx0 = fmaxf(mx0, __shfl_xor_sync(0xFFFFFFFFu, mx0, 2));
    mx1 = fmaxf(mx1, __shfl_xor_sync(0xFFFFFFFFu, mx1, 1));
    mx1 = fmaxf(mx1, __shfl_xor_sync(0xFFFFFFFFu, mx1, 2));

    float sum0 = 0.f, sum1 = 0.f;
#pragma unroll
    for (int nf = 0; nf < NF; nf++) {
        if (nf < NFW) {
            sc[nf][0] = fast_exp(sc[nf][0] - mx0);
            sc[nf][1] = fast_exp(sc[nf][1] - mx0);
            sc[nf][2] = fast_exp(sc[nf][2] - mx1);
            sc[nf][3] = fast_exp(sc[nf][3] - mx1);
            sum0 += sc[nf][0] + sc[nf][1];
            sum1 += sc[nf][2] + sc[nf][3];
        }
    }
    sum0 += __shfl_xor_sync(0xFFFFFFFFu, sum0, 1);
    sum0 += __shfl_xor_sync(0xFFFFFFFFu, sum0, 2);
    sum1 += __shfl_xor_sync(0xFFFFFFFFu, sum1, 1);
    sum1 += __shfl_xor_sync(0xFFFFFFFFu, sum1, 2);
    float inv0 = (qr0 == 0) ? 0.f : 1.f / fmaxf(sum0, 1e-37f);
    float inv1 = 1.f / fmaxf(sum1, 1e-37f);

    float oa[8][4];
#pragma unroll
    for (int nv = 0; nv < 8; nv++)
        oa[nv][0] = oa[nv][1] = oa[nv][2] = oa[nv][3] = 0.f;

#pragma unroll
    for (int kc = 0; kc < NKC; kc++) {
        if (kc < KCW) {
            uint32_t ph[4], pl[4];
            splitpack(sc[2 * kc][0] * inv0, sc[2 * kc][1] * inv0, ph[0], pl[0]);
            splitpack(sc[2 * kc][2] * inv1, sc[2 * kc][3] * inv1, ph[1], pl[1]);
            if (2 * kc + 1 < NF) {
                splitpack(sc[2 * kc + 1][0] * inv0, sc[2 * kc + 1][1] * inv0, ph[2], pl[2]);
                splitpack(sc[2 * kc + 1][2] * inv1, sc[2 * kc + 1][3] * inv1, ph[3], pl[3]);
            } else {
                ph[2] = ph[3] = pl[2] = pl[3] = 0u;
            }
#pragma unroll
            for (int nv = 0; nv < 8; nv++) {
                const int o = (8 * nv + g) * 216 + 16 * kc + 2 * q;
                uint32_t vb[2], vl2[2];
                vb[0]  = *(const uint32_t*)&smb[48384 + o];
                vb[1]  = *(const uint32_t*)&smb[48384 + o + 8];
                vl2[0] = *(const uint32_t*)&smb[62208 + o];
                vl2[1] = *(const uint32_t*)&smb[62208 + o + 8];
                MMA16816(oa[nv], ph, vb);
                MMA16816(oa[nv], ph, vl2);
                MMA16816(oa[nv], pl, vb);
            }
        }
    }

    const int bbb = bh >> 3, hh = bh & 7;
#pragma unroll
    for (int nv = 0; nv < 8; nv++) {
        const int df = 8 * nv + 2 * q;
        {
            const size_t o = ((size_t)bbb * Sk + qr0) * Dk + hh * 64 + df;
            bf16 a = __float2bfloat16(oa[nv][0]);
            bf16 b = __float2bfloat16(oa[nv][1]);
            *(__nv_bfloat162*)&g_chi[o] = __halves2bfloat162(a, b);
            *(__nv_bfloat162*)&g_clo[o] = __halves2bfloat162(
                __float2bfloat16(oa[nv][0] - __bfloat162float(a)),
                __float2bfloat16(oa[nv][1] - __bfloat162float(b)));
        }
        if (qr1 < Sk) {
            const size_t o = ((size_t)bbb * Sk + qr1) * Dk + hh * 64 + df;
            bf16 a = __float2bfloat16(oa[nv][2]);
            bf16 b = __float2bfloat16(oa[nv][3]);
            *(__nv_bfloat162*)&g_chi[o] = __halves2bfloat162(a, b);
            *(__nv_bfloat162*)&g_clo[o] = __halves2bfloat162(
                __float2bfloat16(oa[nv][2] - __bfloat162float(a)),
                __float2bfloat16(oa[nv][3] - __bfloat162float(b)));
        }
    }
}

// ---------------- launch ----------------
extern "C" void kernel_launch(void* const* d_in, const int* in_sizes, int n_in,
                              void* d_out, int out_size)
{
    const float* q  = (const float*)d_in[0];
    const float* k  = (const float*)d_in[1];
    const float* v  = (const float*)d_in[2];
    const float* Wq = (const float*)d_in[3];
    const float* bq = (const float*)d_in[4];
    const float* Wk = (const float*)d_in[5];
    const float* bk = (const float*)d_in[6];
    const float* Wv = (const float*)d_in[7];
    const float* bv = (const float*)d_in[8];
    const float* Wo = (const float*)d_in[9];
    const float* bo = (const float*)d_in[10];
    float* out = (float*)d_out;

    const int nx4 = ROWS * Dk / 4;
    const int nw4 = Dk * Dk / 4;
    cvt_kernel<<<nx4 / 256, 256>>>(q,  0, nx4);
    cvt_kernel<<<nx4 / 256, 256>>>(k,  1, nx4);
    cvt_kernel<<<nx4 / 256, 256>>>(v,  2, nx4);
    cvt_kernel<<<nw4 / 256, 256>>>(Wq, 3, nw4);
    cvt_kernel<<<nw4 / 256, 256>>>(Wk, 4, nw4);
    cvt_kernel<<<nw4 / 256, 256>>>(Wv, 5, nw4);
    cvt_kernel<<<nw4 / 256, 256>>>(Wo, 6, nw4);

    cudaFuncSetAttribute(qkv_mma_kernel, cudaFuncAttributeMaxDynamicSharedMemorySize,
                         GEMM_SMEM);
    qkv_mma_kernel<<<dim3(Dk / 256, ROWS / 128, 3), 512, GEMM_SMEM>>>(bq, bk, bv);

    cudaFuncSetAttribute(attn_mma_kernel<0>, cudaFuncAttributeMaxDynamicSharedMemorySize,
                         ATTN_SMEM);
    cudaFuncSetAttribute(attn_mma_kernel<1>, cudaFuncAttributeMaxDynamicSharedMemorySize,
                         ATTN_SMEM);
    attn_mma_kernel<0><<<Bk * Hk, 256, ATTN_SMEM>>>();
    attn_mma_kernel<1><<<Bk * Hk, 256, ATTN_SMEM>>>();

    cudaFuncSetAttribute(out_mma_kernel, cudaFuncAttributeMaxDynamicSharedMemorySize,
                         GEMM_SMEM);
    out_mma_kernel<<<dim3(Dk / 256, ROWS / 128, 1), 512, GEMM_SMEM>>>(bo, out);
}